// round 8
// baseline (speedup 1.0000x reference)
#include <cuda_runtime.h>
#include <math_constants.h>

#define BB 64
#define NN 64
#define TT 100
#define TS 8                        // t-slices resident per loop iteration
#define NITER 13                    // ceil(TT / TS)

__global__ __launch_bounds__(TS * BB) void social_persist_kernel(
    const float* __restrict__ x,
    const float* __restrict__ wfa,
    const int*   __restrict__ rand_idx,
    const int*   __restrict__ drop_mask,
    float*       __restrict__ out)
{
    const int n    = blockIdx.x;              // 0..63
    const int tid  = threadIdx.x;             // 0..511
    const int tsub = tid >> 6;                // 0..7
    const int b    = tid & 63;                // 0..63
    const int lane = tid & 31;
    const int base = b & 32;                  // which b-half this warp owns

    __shared__ float4 s[TS][BB];              // 8 KB
    __shared__ float  red[TS][BB];            // 2 KB

    // Per-batch transform R, trans (64 distinct rows, L1-hot)
    const float* w = wfa + b * 9;
    const float r00 = w[0], r01 = w[1], tx = w[2];
    const float r10 = w[3], r11 = w[4], ty = w[5];

    float acc = 0.0f;
    int t = tsub;

    // Prefetch first position: x[b, n, t, 0:2] (8B-aligned: offset multiple of 24B)
    float2 cur = make_float2(0.0f, 0.0f);
    if (t < TT) cur = *(const float2*)(x + (((size_t)(b * NN + n)) * TT + t) * 6);

    for (int k = 0; k < NITER; ++k, t += TS) {
        const bool active = (t < TT);         // uniform per warp (t dep. on tsub only)

        float gx = 0.0f, gy = 0.0f, sq = 0.0f;
        if (active) {
            gx = fmaf(r00, cur.x, r01 * cur.y) + tx;
            gy = fmaf(r10, cur.x, r11 * cur.y) + ty;
            sq = fmaf(gx, gx, gy * gy);
            s[tsub][b] = make_float4(gx, gy, sq, 0.0f);
        }

        // Control loads for this t (warp-coalesced in b)
        int ri = 0, drop = 1;
        if (active) {
            const int idx = (t * NN + n) * BB + b;  // row = t*N + n, col = b
            ri   = rand_idx[idx];
            drop = drop_mask[idx];
        }

        // Software-pipeline: prefetch next iteration's position now
        const int t2 = t + TS;
        if (t2 < TT) cur = *(const float2*)(x + (((size_t)(b * NN + n)) * TT + t2) * 6);

        __syncthreads();                      // s[tsub][*] published

        if (active) {
            // My two candidates (c = lane, c = lane+32), premultiplied by -2.
            const float4 caf = s[tsub][lane];
            const float4 cbf = s[tsub][lane + 32];
            const float ca2x = -2.0f * caf.x, ca2y = -2.0f * caf.y, caz = caf.z;
            const float cb2x = -2.0f * cbf.x, cb2y = -2.0f * cbf.y, cbz = cbf.z;

            // Compacted argmin: only lanes with drop==0 (~20%) need it.
            // Key = clamp(d2,1e-12) > 0 -> float bits order-preserving; pack c
            // into the 6 low mantissa bits; REDUX.MIN over the warp. Low-bit
            // index breaks ties toward smaller c (jnp.argmin first-occurrence).
            unsigned int my_cmin = 0;
            const unsigned need = __ballot_sync(0xffffffffu, drop == 0);
            for (unsigned m = need; m; m &= m - 1u) {
                const int tb = __ffs(m) - 1;            // target lane
                const float4 tg = s[tsub][base | tb];   // broadcast LDS

                float k1 = fmaf(tg.x, ca2x, fmaf(tg.y, ca2y, caz)) + tg.z;
                float k2 = fmaf(tg.x, cb2x, fmaf(tg.y, cb2y, cbz)) + tg.z;
                k1 = fmaxf(k1, 1e-12f);
                k2 = fmaxf(k2, 1e-12f);
                unsigned uk1 = (__float_as_uint(k1) & 0xFFFFFFC0u) | (unsigned)lane;
                unsigned uk2 = (__float_as_uint(k2) & 0xFFFFFFC0u) | (unsigned)(lane + 32);

                // Diagonal: candidate c == target_b sits at lane==tb, in the
                // half selected by base.
                if (lane == tb) { if (base) uk2 = 0xFFFFFFFFu; else uk1 = 0xFFFFFFFFu; }

                const unsigned best = __reduce_min_sync(0xffffffffu, min(uk1, uk2));
                if (tb == lane) my_cmin = best & 63u;
            }

            const int rnb = ri + (ri >= b ? 1 : 0);
            const int nb  = drop ? rnb : (int)my_cmin;

            const float4 p  = s[tsub][nb];
            const float  d2 = (sq + p.z) - 2.0f * fmaf(gx, p.x, gy * p.y);
            const float  nd = sqrtf(fmaxf(d2, 1e-12f));
            const float  df = nd - 1.5f;
            acc += df * df;
        }

        __syncthreads();                      // before next iter overwrites s
    }

    red[tsub][b] = acc;
    __syncthreads();

    if (tsub == 0) {
        float tot = 0.0f;
        #pragma unroll
        for (int j = 0; j < TS; ++j) tot += red[j][b];
        out[b * NN + n] = tot * (1.0f / (float)TT);
    }
}

extern "C" void kernel_launch(void* const* d_in, const int* in_sizes, int n_in,
                              void* d_out, int out_size)
{
    const float* x    = (const float*)d_in[0];
    const float* wfa  = (const float*)d_in[1];
    const int*   ridx = (const int*)d_in[2];
    const int*   mask = (const int*)d_in[3];
    float*       out  = (float*)d_out;

    social_persist_kernel<<<NN, TS * BB>>>(x, wfa, ridx, mask, out);
}